// round 10
// baseline (speedup 1.0000x reference)
#include <cuda_runtime.h>

#define BB 4
#define NPTS 2048
#define HH 128
#define WW 128
#define SPLITS 32
#define KCH (NPTS / SPLITS)   // 64 atoms per (s,b)
#define CHUNK 32              // atoms resident in shared at once
#define IMG (BB * HH * WW)    // 65536
#define IMG4 (IMG / 4)        // 16384
#define IMGB (HH * WW)        // 16384
#define IMGB4 (IMGB / 4)      // 4096

// Split-K partials: 8 MB (no device allocations allowed)
__device__ float g_part[SPLITS * BB * HH * WW];

// ---------------------------------------------------------------------------
// Fused kernel, column-halved (unchanged from round 9 — measured ~6.3us).
// Block (s, b, hf) accumulates its 64 atoms into columns [64*hf, 64*hf+64).
// Warp w owns rows [16w, 16w+16); thread tile 8 rows x 4 cols. Atom is
// processed only if its y-support hits the warp's window AND its x-support
// hits this column half (skipped atoms are exactly zero on this tile).
// ---------------------------------------------------------------------------
__global__ void __launch_bounds__(256) fused_kernel(const float* __restrict__ x,
                                                    const float* __restrict__ rot) {
    int s  = blockIdx.x;
    int b  = blockIdx.y;
    int hf = blockIdx.z;             // column half (0/1)
    float colbase = 64.0f * hf;

    __shared__ float sfy[CHUNK][128];   // 16KB  (all rows)
    __shared__ float sfx[CHUNK][64];    // 8KB   (this half's cols)
    __shared__ float spx[CHUNK];
    __shared__ float spy[CHUNK];
    __shared__ unsigned swm[8];         // per-row-window atom bitmap
    __shared__ unsigned sxm;            // this-half atom bitmap

    int tid  = threadIdx.x;
    int w    = tid >> 5;      // warp id = 16-row window (0..7)
    int lane = tid & 31;
    int rg   = lane >> 4;     // row sub-group: rows 16w+8rg .. +8
    int cx   = lane & 15;     // 4-col group within the 64-col half

    const float* R = rot + b * 9;
    float R0 = R[0], R1 = R[1], R2 = R[2];
    float R3 = R[3], R4 = R[4], R5 = R[5];

    float acc[8][4];
#pragma unroll
    for (int i = 0; i < 8; i++)
#pragma unroll
        for (int j = 0; j < 4; j++) acc[i][j] = 0.0f;

    int atom_base = b * NPTS + s * KCH;

    for (int c = 0; c < KCH / CHUNK; c++) {
        // --- Phase A: warp 0 projects 32 atoms, builds bitmaps ---
        if (tid < 32) {
            const float* xp = x + (atom_base + c * CHUNK + tid) * 3;
            float x0 = xp[0], x1 = xp[1], x2 = xp[2];
            const float scale = 51.2f;
            float px = fmaf(R0, x0, fmaf(R1, x1, R2 * x2)) * scale + 64.0f;
            float py = fmaf(R3, x0, fmaf(R4, x1, R5 * x2)) * scale + 64.0f;
            spx[tid] = px;
            spy[tid] = py;
            int w0 = (int)floorf((py - 12.0f) * 0.0625f);
            int w1 = (int)floorf((py + 12.0f) * 0.0625f);
            if (w0 < 0) w0 = 0;
            if (w1 > 7) w1 = 7;
#pragma unroll
            for (int ww = 0; ww < 8; ww++) {
                unsigned bm = __ballot_sync(0xffffffffu, ww >= w0 && ww <= w1);
                if (tid == ww) swm[ww] = bm;
            }
            unsigned hx = __ballot_sync(0xffffffffu,
                                        px > colbase - 12.0f && px < colbase + 75.0f);
            if (tid == 0) sxm = hx;
        }
        __syncthreads();

        // --- Phase B: factor tables (cutoff d^2>=144 -> exp ~ 1e-14) ---
        const float cexp = -0.22222222f;  // -1/(2*1.5^2)
#pragma unroll 4
        for (int i = 0; i < 16; i++) {    // sfy: 4096 entries
            int e = tid + i * 256;
            int a = e >> 7;
            int p = e & 127;
            float dy = (float)p - spy[a];
            float qy = dy * dy;
            sfy[a][p] = (qy < 144.0f) ? __expf(qy * cexp) : 0.0f;
        }
#pragma unroll 4
        for (int i = 0; i < 8; i++) {     // sfx: 2048 entries (this half)
            int e = tid + i * 256;
            int a = e >> 6;
            int pl = e & 63;
            float dx = (colbase + (float)pl) - spx[a];
            float qx = dx * dx;
            sfx[a][pl] = (qx < 144.0f) ? __expf(qx * cexp) : 0.0f;
        }
        __syncthreads();

        // --- Phase C: sparse rank update ---
        unsigned m = swm[w] & sxm;
        int rowbase = 16 * w + 8 * rg;
        while (m) {
            int kk = __ffs(m) - 1;
            m &= m - 1;
            float yv[8], xv[4];
            *(float4*)&yv[0] = *(float4*)&sfy[kk][rowbase];      // broadcast
            *(float4*)&yv[4] = *(float4*)&sfy[kk][rowbase + 4];
            *(float4*)&xv[0] = *(float4*)&sfx[kk][cx * 4];
#pragma unroll
            for (int i = 0; i < 8; i++)
#pragma unroll
                for (int j = 0; j < 4; j++)
                    acc[i][j] = fmaf(yv[i], xv[j], acc[i][j]);
        }
        __syncthreads();
    }

    // --- Epilogue: store this half's partial tile ---
    float* out = g_part + (s * BB + b) * IMGB + 64 * hf;
#pragma unroll
    for (int i = 0; i < 8; i++) {
        int h = 16 * w + 8 * rg + i;
        float4 v = make_float4(acc[i][0], acc[i][1], acc[i][2], acc[i][3]);
        *(float4*)&out[h * WW + cx * 4] = v;
    }
}

// ---------------------------------------------------------------------------
// Combine v4: one LDG.128 per THREAD (latency hidden by 524K threads, not
// per-thread ILP), shared-memory tree over the 32-split dimension.
// Block = 256 threads = 32 splits x 8 outputs. Grid = 2048 blocks.
// ---------------------------------------------------------------------------
__global__ void __launch_bounds__(256) combine_kernel(const float* __restrict__ noise,
                                                      const float* __restrict__ rot,
                                                      float* __restrict__ out) {
    __shared__ float4 sm[256];
    int tid = threadIdx.x;
    int sp  = tid >> 3;                  // split 0..31
    int ol  = tid & 7;                   // output slot within block
    int o   = blockIdx.x * 8 + ol;       // output float4 index, < IMG4
    int b   = o >> 12;                   // IMGB4 = 4096
    int p4  = o & 4095;

    sm[tid] = ((const float4*)g_part)[(sp * BB + b) * IMGB4 + p4];
    __syncthreads();

#pragma unroll
    for (int off = 128; off >= 8; off >>= 1) {
        if (tid < off) {
            float4 a = sm[tid], c = sm[tid + off];
            a.x += c.x; a.y += c.y; a.z += c.z; a.w += c.w;
            sm[tid] = a;
        }
        __syncthreads();
    }

    if (tid < 8) {                       // here ol == tid, o consistent
        float4 s  = sm[tid];
        float4 nz = ((const float4*)noise)[o];
        float4 noisy = make_float4(fmaf(nz.x, 0.1f, s.x), fmaf(nz.y, 0.1f, s.y),
                                   fmaf(nz.z, 0.1f, s.z), fmaf(nz.w, 0.1f, s.w));
        ((float4*)out)[o] = noisy;                       // noisy
        *(float4*)&out[IMG + 36 + o * 4] = s;            // clean (65572 % 4 == 0)
    }
    if (blockIdx.x == 0 && tid < 36) out[IMG + tid] = rot[tid];
}

// ---------------------------------------------------------------------------
extern "C" void kernel_launch(void* const* d_in, const int* in_sizes, int n_in,
                              void* d_out, int out_size) {
    const float* x     = (const float*)d_in[0];  // (4,2048,3)
    const float* rot   = (const float*)d_in[1];  // (4,3,3)
    const float* noise = (const float*)d_in[2];  // (4,128,128)
    float* out = (float*)d_out;

    dim3 grid(SPLITS, BB, 2);
    fused_kernel<<<grid, 256>>>(x, rot);

    combine_kernel<<<IMG4 / 8, 256>>>(noise, rot, out);
}

// round 11
// speedup vs baseline: 1.0470x; 1.0470x over previous
#include <cuda_runtime.h>

#define BB 4
#define NPTS 2048
#define HH 128
#define WW 128
#define SPLITS 32
#define KCH (NPTS / SPLITS)   // 64 atoms per (s,b)
#define CHUNK 32              // atoms resident in shared at once
#define IMG (BB * HH * WW)    // 65536
#define IMGB4 (HH * WW / 4)   // 4096 float4 per batch
#define CLEAN_OFF (IMG + 36)  // float4-aligned (65572 % 4 == 0)

// Split-K partials (8 MB) + group barriers. Zero-init at load; counters are
// self-resetting per run, so graph replays and the correctness call all work.
__device__ float g_part[SPLITS * BB * HH * WW];
__device__ int   g_cnt[8];    // arrive counters, one per (b,hf) group
__device__ int   g_done[8];   // combine-done counters (last block resets both)

// ---------------------------------------------------------------------------
// Single kernel. Block (s,b,hf): sparse outer-product of its 64 atoms into a
// 128x64 register tile -> g_part; group barrier over the 32 blocks of (b,hf);
// then those 32 blocks cooperatively reduce the group's outputs from hot L2.
// ---------------------------------------------------------------------------
__global__ void __launch_bounds__(256, 2)
fused_kernel(const float* __restrict__ x,
             const float* __restrict__ rot,
             const float* __restrict__ noise,
             float* __restrict__ out) {
    int s  = blockIdx.x;
    int b  = blockIdx.y;
    int hf = blockIdx.z;             // column half (0/1)
    float colbase = 64.0f * hf;

    __shared__ float sfy[CHUNK][128];   // 16KB  (all rows)
    __shared__ float sfx[CHUNK][64];    // 8KB   (this half's cols)
    __shared__ float spx[CHUNK];
    __shared__ float spy[CHUNK];
    __shared__ unsigned swm[8];         // per-row-window atom bitmap
    __shared__ unsigned sxm;            // this-half atom bitmap

    int tid  = threadIdx.x;
    int w    = tid >> 5;      // warp id = 16-row window (0..7)
    int lane = tid & 31;
    int rg   = lane >> 4;     // row sub-group: rows 16w+8rg .. +8
    int cx   = lane & 15;     // 4-col group within the 64-col half

    // Rot passthrough (independent of everything else)
    if (s == 0 && b == 0 && hf == 0 && tid < 36) out[IMG + tid] = rot[tid];

    const float* R = rot + b * 9;
    float R0 = R[0], R1 = R[1], R2 = R[2];
    float R3 = R[3], R4 = R[4], R5 = R[5];

    float acc[8][4];
#pragma unroll
    for (int i = 0; i < 8; i++)
#pragma unroll
        for (int j = 0; j < 4; j++) acc[i][j] = 0.0f;

    int atom_base = b * NPTS + s * KCH;

    for (int c = 0; c < KCH / CHUNK; c++) {
        // --- Phase A: warp 0 projects 32 atoms, builds bitmaps ---
        if (tid < 32) {
            const float* xp = x + (atom_base + c * CHUNK + tid) * 3;
            float x0 = xp[0], x1 = xp[1], x2 = xp[2];
            const float scale = 51.2f;
            float px = fmaf(R0, x0, fmaf(R1, x1, R2 * x2)) * scale + 64.0f;
            float py = fmaf(R3, x0, fmaf(R4, x1, R5 * x2)) * scale + 64.0f;
            spx[tid] = px;
            spy[tid] = py;
            int w0 = (int)floorf((py - 12.0f) * 0.0625f);
            int w1 = (int)floorf((py + 12.0f) * 0.0625f);
            if (w0 < 0) w0 = 0;
            if (w1 > 7) w1 = 7;
#pragma unroll
            for (int ww = 0; ww < 8; ww++) {
                unsigned bm = __ballot_sync(0xffffffffu, ww >= w0 && ww <= w1);
                if (tid == ww) swm[ww] = bm;
            }
            unsigned hx = __ballot_sync(0xffffffffu,
                                        px > colbase - 12.0f && px < colbase + 75.0f);
            if (tid == 0) sxm = hx;
        }
        __syncthreads();

        // --- Phase B: factor tables (cutoff d^2>=144 -> exp ~ 1e-14) ---
        const float cexp = -0.22222222f;  // -1/(2*1.5^2)
#pragma unroll 4
        for (int i = 0; i < 16; i++) {    // sfy: 4096 entries
            int e = tid + i * 256;
            int a = e >> 7;
            int p = e & 127;
            float dy = (float)p - spy[a];
            float qy = dy * dy;
            sfy[a][p] = (qy < 144.0f) ? __expf(qy * cexp) : 0.0f;
        }
#pragma unroll 4
        for (int i = 0; i < 8; i++) {     // sfx: 2048 entries (this half)
            int e = tid + i * 256;
            int a = e >> 6;
            int pl = e & 63;
            float dx = (colbase + (float)pl) - spx[a];
            float qx = dx * dx;
            sfx[a][pl] = (qx < 144.0f) ? __expf(qx * cexp) : 0.0f;
        }
        __syncthreads();

        // --- Phase C: sparse rank update ---
        unsigned m = swm[w] & sxm;
        int rowbase = 16 * w + 8 * rg;
        while (m) {
            int kk = __ffs(m) - 1;
            m &= m - 1;
            float yv[8], xv[4];
            *(float4*)&yv[0] = *(float4*)&sfy[kk][rowbase];      // broadcast
            *(float4*)&yv[4] = *(float4*)&sfy[kk][rowbase + 4];
            *(float4*)&xv[0] = *(float4*)&sfx[kk][cx * 4];
#pragma unroll
            for (int i = 0; i < 8; i++)
#pragma unroll
                for (int j = 0; j < 4; j++)
                    acc[i][j] = fmaf(yv[i], xv[j], acc[i][j]);
        }
        __syncthreads();
    }

    // --- Store this half's partial tile ---
    float* pdst = g_part + (s * BB + b) * (HH * WW) + 64 * hf;
#pragma unroll
    for (int i = 0; i < 8; i++) {
        int h = 16 * w + 8 * rg + i;
        float4 v = make_float4(acc[i][0], acc[i][1], acc[i][2], acc[i][3]);
        *(float4*)&pdst[h * WW + cx * 4] = v;
    }

    // --- Group barrier: the 32 split-blocks of (b, hf) rendezvous ---
    int gidx = b * 2 + hf;
    __threadfence();                 // each thread: my STGs visible gpu-wide
    __syncthreads();                 // all threads' fences done
    if (tid == 0) {
        atomicAdd(&g_cnt[gidx], 1);
        volatile int* vc = &g_cnt[gidx];
        while (*vc < SPLITS) { }     // all 32 co-resident -> no deadlock
    }
    __syncthreads();

    // --- Cooperative combine: 32 blocks x 256 thr = 8192 threads,
    //     2048 output float4 in this group, 4 threads/output x 8 splits.
    //     Partials are seconds-old L2 lines: __ldcg hits L2.
    {
        int r   = s * 256 + tid;     // group-wide rank
        int ol  = r >> 2;            // output slot 0..2047
        int q   = r & 3;             // split quarter (same warp for an output)
        int row = ol >> 4;
        int c4  = ol & 15;
        int off4 = b * IMGB4 + row * 32 + hf * 16 + c4;

        const float4* pp = (const float4*)g_part + (q * 8 * BB + b) * IMGB4
                           + row * 32 + hf * 16 + c4;
        float4 sv = make_float4(0.f, 0.f, 0.f, 0.f);
#pragma unroll
        for (int j = 0; j < 8; j++) {
            float4 v = __ldcg(pp + j * (BB * IMGB4));
            sv.x += v.x; sv.y += v.y; sv.z += v.z; sv.w += v.w;
        }
#pragma unroll
        for (int off = 1; off <= 2; off <<= 1) {
            sv.x += __shfl_xor_sync(0xffffffffu, sv.x, off);
            sv.y += __shfl_xor_sync(0xffffffffu, sv.y, off);
            sv.z += __shfl_xor_sync(0xffffffffu, sv.z, off);
            sv.w += __shfl_xor_sync(0xffffffffu, sv.w, off);
        }
        if (q == 0) {
            float4 nz = ((const float4*)noise)[off4];
            float4 ny = make_float4(fmaf(nz.x, 0.1f, sv.x), fmaf(nz.y, 0.1f, sv.y),
                                    fmaf(nz.z, 0.1f, sv.z), fmaf(nz.w, 0.1f, sv.w));
            ((float4*)out)[off4] = ny;                   // noisy
            *(float4*)&out[CLEAN_OFF + off4 * 4] = sv;   // clean
        }
    }

    // --- Reset barrier state for the next graph replay ---
    __syncthreads();
    if (tid == 0) {
        int d = atomicAdd(&g_done[gidx], 1);
        if (d == SPLITS - 1) {       // last block of group: reset both
            g_cnt[gidx]  = 0;
            __threadfence();
            g_done[gidx] = 0;
        }
    }
}

// ---------------------------------------------------------------------------
extern "C" void kernel_launch(void* const* d_in, const int* in_sizes, int n_in,
                              void* d_out, int out_size) {
    const float* x     = (const float*)d_in[0];  // (4,2048,3)
    const float* rot   = (const float*)d_in[1];  // (4,3,3)
    const float* noise = (const float*)d_in[2];  // (4,128,128)
    float* out = (float*)d_out;

    dim3 grid(SPLITS, BB, 2);                    // 256 blocks <= 296 resident
    fused_kernel<<<grid, 256>>>(x, rot, noise, out);
}